// round 2
// baseline (speedup 1.0000x reference)
#include <cuda_runtime.h>

#define NTAGS   1024
#define NCTA    128
#define TPB     256
#define ROWS    8          // tag rows per CTA: NCTA*ROWS = 1024
#define TSTEPS  65536
#define NCNT    8          // barrier counters (spread across L2 slices)

// Persistent device state (no allocations allowed).
__device__ __align__(16) float    g_alpha[2][NTAGS];
__device__             unsigned   g_cnt[NCNT * 64];   // stride 256B to spread LTS slices

__device__ __forceinline__ unsigned ld_acq(const unsigned* p) {
    unsigned v;
    asm volatile("ld.acquire.gpu.global.u32 %0, [%1];" : "=r"(v) : "l"(p) : "memory");
    return v;
}
__device__ __forceinline__ void red_rel(unsigned* p, unsigned v) {
    asm volatile("red.release.gpu.global.add.u32 [%0], %1;" :: "l"(p), "r"(v) : "memory");
}

// Register-halving butterfly: sums p[0..7] (one value per row) across the
// full warp in 9 shfls. On return, every lane holds the complete 32-lane sum
// of row  4*(lane&1) + 2*((lane>>1)&1) + ((lane>>2)&1).
__device__ __forceinline__ float warp_sum8(float p[8], int lane) {
    #pragma unroll
    for (int i = 0; i < 4; i++) {
        float lo = p[i], hi = p[i + 4];
        float mine  = (lane & 1) ? lo : hi;
        float other = __shfl_xor_sync(0xffffffffu, mine, 1);
        p[i] = ((lane & 1) ? hi : lo) + other;
    }
    #pragma unroll
    for (int i = 0; i < 2; i++) {
        float lo = p[i], hi = p[i + 2];
        float mine  = (lane & 2) ? lo : hi;
        float other = __shfl_xor_sync(0xffffffffu, mine, 2);
        p[i] = ((lane & 2) ? hi : lo) + other;
    }
    {
        float lo = p[0], hi = p[1];
        float mine  = (lane & 4) ? lo : hi;
        float other = __shfl_xor_sync(0xffffffffu, mine, 4);
        p[0] = ((lane & 4) ? hi : lo) + other;
    }
    p[0] += __shfl_xor_sync(0xffffffffu, p[0], 8);
    p[0] += __shfl_xor_sync(0xffffffffu, p[0], 16);
    return p[0];
}
__device__ __forceinline__ int row_of_lane(int lane) {
    return 4 * (lane & 1) + 2 * ((lane >> 1) & 1) + ((lane >> 2) & 1);
}
__device__ __forceinline__ float warp_max(float x) {
    #pragma unroll
    for (int m = 1; m < 32; m <<= 1)
        x = fmaxf(x, __shfl_xor_sync(0xffffffffu, x, m));
    return x;
}

__global__ void __launch_bounds__(TPB, 1)
crf_kernel(const float* __restrict__ unary,
           const float* __restrict__ trans,
           const int*   __restrict__ start_p,
           const int*   __restrict__ end_p,
           float*       __restrict__ out)
{
    const int tid  = threadIdx.x;
    const int lane = tid & 31;
    const int w    = tid >> 5;          // 8 warps
    const int cta  = blockIdx.x;
    const int base = cta * ROWS;        // first tag row owned by this CTA
    const int sidx = __ldg(start_p);

    __shared__ float s_p[8][8];         // [warp][row] partial dot sums
    __shared__ float s_m[8];            // [warp] partial maxes

    // ---- Preload E = exp(transitions) into registers -------------------
    // Thread owns columns j in [4*tid, 4*tid+4) for all 8 of this CTA's rows.
    float E[ROWS][4];
    #pragma unroll
    for (int r = 0; r < ROWS; r++) {
        const float4 tr = *reinterpret_cast<const float4*>(
            &trans[(size_t)(base + r) * NTAGS + 4 * tid]);
        E[r][0] = __expf(tr.x); E[r][1] = __expf(tr.y);
        E[r][2] = __expf(tr.z); E[r][3] = __expf(tr.w);
    }

    float m      = 8.0f;   // exp-offset for step 1 (bounds max(alpha_0) <= ~6)
    float u_next = 0.0f;   // prefetched unary (valid for tid < 8)

    // ---- Step 0: v = one-hot(start_idx), offset 0 -----------------------
    {
        float p[ROWS];
        #pragma unroll
        for (int r = 0; r < ROWS; r++) {
            p[r] = 0.0f;
            #pragma unroll
            for (int c = 0; c < 4; c++)
                if (4 * tid + c == sidx) p[r] = E[r][c];
        }
        const float psum = warp_sum8(p, lane);
        if (lane < 8) s_p[w][row_of_lane(lane)] = psum;

        if (tid < ROWS)   // prefetch unary row 1
            u_next = __ldcs(&unary[(size_t)1 * NTAGS + base + tid]);
        __syncthreads();
        if (tid < ROWS) {
            float s = s_p[0][tid];
            #pragma unroll
            for (int w2 = 1; w2 < 8; w2++) s += s_p[w2][tid];
            float u0 = __ldcs(&unary[(size_t)0 * NTAGS + base + tid]);
            g_alpha[0][base + tid] = __logf(s) + u0;   // == Tr[row,start] + u0
        }
        __syncthreads();
        if (tid == 0) red_rel(&g_cnt[(cta & (NCNT - 1)) * 64], 1u);
    }

    // ---- Main scan -----------------------------------------------------
    for (int t = 1; t < TSTEPS; t++) {
        // Wait until all CTAs published alpha_{t-1}.
        if (tid < NCNT) {
            const unsigned tgt = 16u * (unsigned)t;   // 128/NCNT CTAs per counter
            while (ld_acq(&g_cnt[tid * 64]) < tgt) {}
        }
        __syncthreads();

        const float4 av = __ldcg(reinterpret_cast<const float4*>(
            &g_alpha[(t - 1) & 1][4 * tid]));

        // Prefetch next unary while the exp/dot chain runs.
        const float u_cur = u_next;
        if (tid < ROWS) {
            const int tn = (t + 1 < TSTEPS) ? t + 1 : t;
            u_next = __ldcs(&unary[(size_t)tn * NTAGS + base + tid]);
        }

        const float v0 = __expf(av.x - m), v1 = __expf(av.y - m);
        const float v2 = __expf(av.z - m), v3 = __expf(av.w - m);
        float lm = fmaxf(fmaxf(av.x, av.y), fmaxf(av.z, av.w));

        float p[ROWS];
        #pragma unroll
        for (int r = 0; r < ROWS; r++)
            p[r] = fmaf(E[r][3], v3,
                   fmaf(E[r][2], v2,
                   fmaf(E[r][1], v1, E[r][0] * v0)));

        const float psum = warp_sum8(p, lane);
        lm = warp_max(lm);

        if (lane < 8) s_p[w][row_of_lane(lane)] = psum;
        if (lane == 0) s_m[w] = lm;
        __syncthreads();

        if (tid < ROWS) {
            float s = s_p[0][tid];
            #pragma unroll
            for (int w2 = 1; w2 < 8; w2++) s += s_p[w2][tid];
            g_alpha[t & 1][base + tid] = __logf(s) + m + u_cur;
        }

        // Offset for step t+1: bounds max(alpha_t) since per-step drift < 20.
        float mm = s_m[0];
        #pragma unroll
        for (int w2 = 1; w2 < 8; w2++) mm = fmaxf(mm, s_m[w2]);
        m = mm + 20.0f;

        __syncthreads();                       // order the 8 stores before release
        if (tid == 0) red_rel(&g_cnt[(cta & (NCNT - 1)) * 64], 1u);
    }

    // ---- Terminal logsumexp (CTA 0 only) -------------------------------
    if (cta == 0) {
        if (tid < NCNT) {
            const unsigned tgt = 16u * (unsigned)TSTEPS;
            while (ld_acq(&g_cnt[tid * 64]) < tgt) {}
        }
        __syncthreads();

        const int eidx = __ldg(end_p);
        const float4 av = __ldcg(reinterpret_cast<const float4*>(
            &g_alpha[(TSTEPS - 1) & 1][4 * tid]));
        const float4 tr = *reinterpret_cast<const float4*>(
            &trans[(size_t)eidx * NTAGS + 4 * tid]);
        const float x0 = av.x + tr.x, x1 = av.y + tr.y;
        const float x2 = av.z + tr.z, x3 = av.w + tr.w;

        float lm = fmaxf(fmaxf(x0, x1), fmaxf(x2, x3));
        lm = warp_max(lm);
        if (lane == 0) s_m[w] = lm;
        __syncthreads();
        float M = s_m[0];
        #pragma unroll
        for (int w2 = 1; w2 < 8; w2++) M = fmaxf(M, s_m[w2]);

        float s = __expf(x0 - M) + __expf(x1 - M) + __expf(x2 - M) + __expf(x3 - M);
        #pragma unroll
        for (int msk = 1; msk < 32; msk <<= 1)
            s += __shfl_xor_sync(0xffffffffu, s, msk);
        if (lane == 0) s_p[w][0] = s;
        __syncthreads();

        if (tid == 0) {
            float S = s_p[0][0];
            #pragma unroll
            for (int w2 = 1; w2 < 8; w2++) S += s_p[w2][0];
            out[0] = __logf(S) + M;
            // Reset barrier counters so the next graph replay starts clean.
            #pragma unroll
            for (int c = 0; c < NCNT; c++) g_cnt[c * 64] = 0u;
        }
    }
}

extern "C" void kernel_launch(void* const* d_in, const int* in_sizes, int n_in,
                              void* d_out, int out_size)
{
    const float* unary = (const float*)d_in[0];   // [65536, 1024] f32
    const float* trans = (const float*)d_in[1];   // [1024, 1024]  f32
    const int*   sidx  = (const int*)d_in[2];     // scalar
    const int*   eidx  = (const int*)d_in[3];     // scalar
    float*       out   = (float*)d_out;           // scalar f32

    crf_kernel<<<NCTA, TPB>>>(unary, trans, sidx, eidx, out);
}